// round 5
// baseline (speedup 1.0000x reference)
#include <cuda_runtime.h>
#include <math.h>
#include <stdint.h>

// ---------------------------------------------------------------------------
// Problem constants
// ---------------------------------------------------------------------------
#define Nn 16            // B*T
#define Cc 512
#define Ss 1024          // H*W
#define NHEADS 8
#define HD 64
#define D3 1536          // 3*C

// All GEMM k-dimensions are stored "k-permuted": within each aligned 32-chunk,
// element k sits at position (k%4)*8 + k/4.  Then the 8 elements lane (tg)
// needs for 4 consecutive m16n8k8 k-steps are contiguous at offset tg*8,
// enabling float4 fragment loads from SMEM.
__device__ __forceinline__ int kperm(int k) {
    return (k & ~31) + (k & 3) * 8 + ((k & 31) >> 2);
}

// ---------------------------------------------------------------------------
// Scratch (device globals; no cudaMalloc allowed)
// ---------------------------------------------------------------------------
__device__ float g_hn   [Nn * Ss * Cc];           // [n][s][c-perm] tf32
__device__ float g_q    [Nn * NHEADS * Ss * HD];  // [nh][s][e-perm] tf32
__device__ float g_k    [Nn * NHEADS * Ss * HD];  // [nh][s][e-perm] tf32
__device__ float g_v    [Nn * NHEADS * HD * Ss];  // [nh][e][s-perm] tf32
__device__ float g_att  [Nn * Ss * Cc];           // [n][s][c-perm] tf32
__device__ float g_wqkvT[D3 * Cc];                // [d][c-perm] tf32
__device__ float g_woutT[Cc * Cc];                // [c2][c-perm] tf32

// ---------------------------------------------------------------------------
// Helpers
// ---------------------------------------------------------------------------
__device__ __forceinline__ uint32_t smem_u32(const void* p) {
    uint32_t a;
    asm("{ .reg .u64 t; cvta.to.shared.u64 t, %1; cvt.u32.u64 %0, t; }"
        : "=r"(a) : "l"(p));
    return a;
}

__device__ __forceinline__ float tf32r(float x) {
    uint32_t u;
    asm("cvt.rna.tf32.f32 %0, %1;" : "=r"(u) : "f"(x));
    return __uint_as_float(u);
}

__device__ __forceinline__ uint32_t fau(float x) { return __float_as_uint(x); }

// m16n8k8 tf32 mma, D = A*B + D (in place)
__device__ __forceinline__ void mma8(float* d, const uint32_t* a, const uint32_t* b) {
    asm volatile(
        "mma.sync.aligned.m16n8k8.row.col.f32.tf32.tf32.f32 "
        "{%0,%1,%2,%3}, {%4,%5,%6,%7}, {%8,%9}, {%0,%1,%2,%3};"
        : "+f"(d[0]), "+f"(d[1]), "+f"(d[2]), "+f"(d[3])
        : "r"(a[0]), "r"(a[1]), "r"(a[2]), "r"(a[3]), "r"(b[0]), "r"(b[1]));
}

__device__ __forceinline__ void cp16(uint32_t dst, const void* src) {
    asm volatile("cp.async.cg.shared.global [%0], [%1], 16;" :: "r"(dst), "l"(src));
}
#define CP_COMMIT() asm volatile("cp.async.commit_group;" ::: "memory")
#define CP_WAIT1()  asm volatile("cp.async.wait_group 1;" ::: "memory")

// ---------------------------------------------------------------------------
// Kernel 0: weight transpose + tf32 rounding + k-permute.
//   in [512][Ccols] -> out [Ccols][512], columns (k=c) permuted per 32-chunk.
// ---------------------------------------------------------------------------
__global__ void __launch_bounds__(256) trans_kernel(const float* __restrict__ in,
                                                    int Ccols, int which)
{
    float* out = which ? g_woutT : g_wqkvT;
    __shared__ float t[32][33];
    int c0 = blockIdx.x * 32, r0 = blockIdx.y * 32;
    int tx = threadIdx.x, ty = threadIdx.y;
#pragma unroll
    for (int i = 0; i < 32; i += 8)
        t[ty + i][tx] = in[(size_t)(r0 + ty + i) * Ccols + c0 + tx];
    __syncthreads();
    int txp = (tx & 3) * 8 + (tx >> 2);     // permuted position within chunk
#pragma unroll
    for (int i = 0; i < 32; i += 8)
        out[(size_t)(c0 + ty + i) * 512 + r0 + txp] = tf32r(t[tx][ty + i]);
}

// ---------------------------------------------------------------------------
// Kernel 1: GroupNorm -> g_hn [n][s][c-perm] (tf32)
// ---------------------------------------------------------------------------
__global__ void __launch_bounds__(256) gn_kernel(const float* __restrict__ x,
                                                 const float* __restrict__ sc,
                                                 const float* __restrict__ bi)
{
    extern __shared__ float smt[];   // [1024][17]
    int n = blockIdx.x >> 5;
    int g = blockIdx.x & 31;
    const float* px = x + (size_t)(n * Cc + g * 16) * Ss;
    // this block's channels g*16..g*16+15 live in 32-chunk (g>>1)*32
    float* ph = g_hn + (size_t)n * Ss * Cc + (g >> 1) * 32;
    int tid = threadIdx.x;
    const int M = 16 * Ss;

    float s = 0.f, ss = 0.f;
    for (int i = tid * 4; i < M; i += 1024) {
        float4 v = *(const float4*)&px[i];
        s  += v.x + v.y + v.z + v.w;
        ss += v.x*v.x + v.y*v.y + v.z*v.z + v.w*v.w;
    }
#pragma unroll
    for (int o = 16; o; o >>= 1) {
        s  += __shfl_xor_sync(0xffffffffu, s,  o);
        ss += __shfl_xor_sync(0xffffffffu, ss, o);
    }
    __shared__ float r0[8], r1[8];
    __shared__ float s_mean, s_inv;
    if ((tid & 31) == 0) { r0[tid >> 5] = s; r1[tid >> 5] = ss; }
    __syncthreads();
    if (tid == 0) {
        float a = 0.f, b2 = 0.f;
#pragma unroll
        for (int i = 0; i < 8; i++) { a += r0[i]; b2 += r1[i]; }
        float mean = a / (float)M;
        float var  = b2 / (float)M - mean * mean;
        s_mean = mean;
        s_inv  = rsqrtf(var + 1e-6f);
    }
    __syncthreads();
    float mean = s_mean, inv = s_inv;

    for (int i = tid * 4; i < M; i += 1024) {
        int c  = i >> 10;
        int sp = i & 1023;
        float scv = sc[g * 16 + c] * inv;
        float biv = bi[g * 16 + c] - mean * scv;
        float4 v = *(const float4*)&px[i];
        smt[(sp + 0) * 17 + c] = tf32r(v.x * scv + biv);
        smt[(sp + 1) * 17 + c] = tf32r(v.y * scv + biv);
        smt[(sp + 2) * 17 + c] = tf32r(v.z * scv + biv);
        smt[(sp + 3) * 17 + c] = tf32r(v.w * scv + biv);
    }
    __syncthreads();

    // permuted write: within chunk, local c32 = (g&1)*16 + cl maps to
    // pos = (cl&3)*8 + (g&1)*4 + cl/4.  float4 #a holds cl = {a, a+4, a+8, a+12}.
    int half = (g & 1) * 4;
#pragma unroll
    for (int j = 0; j < 4; j++) {
        int sp = tid * 4 + j;
        const float* row = &smt[sp * 17];
        float* dst = ph + (size_t)sp * Cc;
#pragma unroll
        for (int a = 0; a < 4; a++) {
            float4 o = make_float4(row[a], row[a + 4], row[a + 8], row[a + 12]);
            *(float4*)&dst[a * 8 + half] = o;
        }
    }
}

// ---------------------------------------------------------------------------
// Kernel 2: tf32 mma.sync GEMM, tile 128x128, K=512, BK=32, 3-stage cp.async.
// float4 fragment loads from k-permuted SMEM (stride 36).
// ---------------------------------------------------------------------------
__device__ __forceinline__ void gemm_load(uint32_t sbase, int soff,
                                          const float* __restrict__ Ag,
                                          const float* __restrict__ Bg,
                                          int koff, int tid)
{
#pragma unroll
    for (int i = 0; i < 4; i++) {
        int f = tid + i * 256;
        int row = f >> 3, c4 = f & 7;
        cp16(sbase + (uint32_t)((soff + row * 36 + c4 * 4) * 4),
             Ag + (size_t)row * Cc + koff + c4 * 4);
        cp16(sbase + (uint32_t)((soff + 4608 + row * 36 + c4 * 4) * 4),
             Bg + (size_t)row * Cc + koff + c4 * 4);
    }
}

__global__ void __launch_bounds__(256, 2) gemm_mma(const float* __restrict__ bias,
                                                   const float* __restrict__ xres,
                                                   float* __restrict__ out,
                                                   int mode)
{
    extern __shared__ float sm[];
    uint32_t sbase = smem_u32(sm);
    int tid = threadIdx.x, lane = tid & 31, wid = tid >> 5;
    int g = lane >> 2, tg = lane & 3;
    int n = blockIdx.z, s0 = blockIdx.x * 128, d0 = blockIdx.y * 128;
    int wm = wid & 3, wn = wid >> 2;

    const float* Ag = (mode ? g_att : g_hn) + ((size_t)n * Ss + s0) * Cc;
    const float* Bg = (mode ? g_woutT : g_wqkvT) + (size_t)d0 * Cc;

    float C[2][8][4] = {};

    gemm_load(sbase, 0, Ag, Bg, 0, tid);
    CP_COMMIT();
    gemm_load(sbase, 9216, Ag, Bg, 32, tid);
    CP_COMMIT();

    for (int kc = 0; kc < 16; kc++) {
        CP_WAIT1();
        __syncthreads();
        int b = kc % 3;
        if (kc + 2 < 16)
            gemm_load(sbase, ((kc + 2) % 3) * 9216, Ag, Bg, (kc + 2) * 32, tid);
        CP_COMMIT();

        const float* As = sm + b * 9216;
        const float* Bs = As + 4608;
#pragma unroll
        for (int kh = 0; kh < 2; kh++) {        // ks-pairs (0,1) and (2,3)
            int off = tg * 8 + kh * 4;
            float4 a4[4];
            a4[0] = *(const float4*)&As[(wm * 32 +      g) * 36 + off];
            a4[1] = *(const float4*)&As[(wm * 32 +  8 + g) * 36 + off];
            a4[2] = *(const float4*)&As[(wm * 32 + 16 + g) * 36 + off];
            a4[3] = *(const float4*)&As[(wm * 32 + 24 + g) * 36 + off];
            uint32_t ae0[4] = {fau(a4[0].x), fau(a4[1].x), fau(a4[0].y), fau(a4[1].y)};
            uint32_t ae1[4] = {fau(a4[2].x), fau(a4[3].x), fau(a4[2].y), fau(a4[3].y)};
            uint32_t ao0[4] = {fau(a4[0].z), fau(a4[1].z), fau(a4[0].w), fau(a4[1].w)};
            uint32_t ao1[4] = {fau(a4[2].z), fau(a4[3].z), fau(a4[2].w), fau(a4[3].w)};
#pragma unroll
            for (int tn = 0; tn < 8; tn++) {
                float4 b4 = *(const float4*)&Bs[(wn * 64 + tn * 8 + g) * 36 + off];
                uint32_t be[2] = {fau(b4.x), fau(b4.y)};
                uint32_t bo[2] = {fau(b4.z), fau(b4.w)};
                mma8(C[0][tn], ae0, be);
                mma8(C[1][tn], ae1, be);
                mma8(C[0][tn], ao0, bo);
                mma8(C[1][tn], ao1, bo);
            }
        }
    }

    // epilogue (permuted stores where the target is a GEMM k-dim)
#pragma unroll
    for (int tm = 0; tm < 2; tm++) {
#pragma unroll
        for (int hh = 0; hh < 2; hh++) {
            int m = s0 + wm * 32 + tm * 16 + g + hh * 8;
#pragma unroll
            for (int tn = 0; tn < 8; tn++) {
                int d = d0 + wn * 64 + tn * 8 + 2 * tg;
                float v0 = C[tm][tn][hh * 2 + 0] + __ldg(&bias[d]);
                float v1 = C[tm][tn][hh * 2 + 1] + __ldg(&bias[d + 1]);
                if (mode == 0) {
                    int head = d / 192, t = d % 192;
                    int part = t >> 6, e = t & 63;
                    size_t nh = (size_t)(n * 8 + head);
                    if (part == 0) {
                        float* dst = &g_q[(nh * Ss + m) * HD];
                        dst[kperm(e)]     = tf32r(v0);
                        dst[kperm(e + 1)] = tf32r(v1);
                    } else if (part == 1) {
                        float* dst = &g_k[(nh * Ss + m) * HD];
                        dst[kperm(e)]     = tf32r(v0);
                        dst[kperm(e + 1)] = tf32r(v1);
                    } else {
                        int mp = kperm(m & 1023) + (m & ~1023);
                        g_v[(nh * HD + e) * Ss + mp]       = tf32r(v0);
                        g_v[(nh * HD + e + 1) * Ss + mp]   = tf32r(v1);
                    }
                } else {
                    size_t gi = ((size_t)n * Cc + d) * Ss + m;
                    out[gi]      = v0 + xres[gi];
                    out[gi + Ss] = v1 + xres[gi + Ss];
                }
            }
        }
    }
}

// ---------------------------------------------------------------------------
// Kernel 3: flash attention, tf32 mma.sync, double-buffered cp.async K/V,
// float4 fragment loads from k-permuted SMEM, shuffle-transposed P.
// ---------------------------------------------------------------------------
#define ATT_SMEM 104448

__device__ __forceinline__ void attn_load_kv(uint32_t sbase, int b,
                                             const float* __restrict__ K,
                                             const float* __restrict__ V,
                                             int kt, int tid)
{
#pragma unroll
    for (int i = 0; i < 4; i++) {
        int f = tid + i * 256;
        int r = f >> 4, c4 = f & 15;
        cp16(sbase + (uint32_t)((b * 8704 + r * 68 + c4 * 4) * 4),
             K + (size_t)(kt * 64 + r) * HD + c4 * 4);
        cp16(sbase + (uint32_t)((b * 8704 + 4352 + r * 68 + c4 * 4) * 4),
             V + (size_t)r * Ss + kt * 64 + c4 * 4);
    }
}

__global__ void __launch_bounds__(256, 2) attn_mma()
{
    extern __shared__ float sm[];
    uint32_t sbase = smem_u32(sm);
    float* Qs = sm + 17408;

    int tid = threadIdx.x, lane = tid & 31, w = tid >> 5;
    int g = lane >> 2, tg = lane & 3;
    int nh = blockIdx.y, q0 = blockIdx.x * 128;
    const float* Q = g_q + (size_t)nh * Ss * HD;
    const float* K = g_k + (size_t)nh * Ss * HD;
    const float* V = g_v + (size_t)nh * HD * Ss;

#pragma unroll
    for (int i = 0; i < 8; i++) {
        int f = tid + i * 256;
        int row = f >> 4, c4 = f & 15;
        cp16(sbase + (uint32_t)((17408 + row * 68 + c4 * 4) * 4),
             Q + (size_t)(q0 + row) * HD + c4 * 4);
    }
    attn_load_kv(sbase, 0, K, V, 0, tid);
    CP_COMMIT();
    attn_load_kv(sbase, 1, K, V, 1, tid);
    CP_COMMIT();

    float O[8][4] = {};
    float m0 = -1e30f, m1 = -1e30f, l0 = 0.f, l1 = 0.f;
    int qb = w * 16;
    int srcA = g * 4 + (tg >> 1);
    int srcB = srcA + 2;
    bool oddc = (tg & 1);

    for (int kt = 0; kt < 16; kt++) {
        CP_WAIT1();
        __syncthreads();
        int b = kt & 1;
        const float* Ks = sm + b * 8704;
        const float* Vs = Ks + 4352;

        // S = Q @ K^T
        float S[8][4] = {};
#pragma unroll
        for (int kp = 0; kp < 4; kp++) {
            int off = (kp >> 1) * 32 + tg * 8 + (kp & 1) * 4;
            float4 q0f = *(const float4*)&Qs[(qb +     g) * 68 + off];
            float4 q1f = *(const float4*)&Qs[(qb + 8 + g) * 68 + off];
            uint32_t ae[4] = {fau(q0f.x), fau(q1f.x), fau(q0f.y), fau(q1f.y)};
            uint32_t ao[4] = {fau(q0f.z), fau(q1f.z), fau(q0f.w), fau(q1f.w)};
#pragma unroll
            for (int tn = 0; tn < 8; tn++) {
                float4 kf = *(const float4*)&Ks[(tn * 8 + g) * 68 + off];
                uint32_t be[2] = {fau(kf.x), fau(kf.y)};
                uint32_t bo[2] = {fau(kf.z), fau(kf.w)};
                mma8(S[tn], ae, be);
                mma8(S[tn], ao, bo);
            }
        }

        // scale + online softmax
        float mx0 = -1e30f, mx1 = -1e30f;
#pragma unroll
        for (int tn = 0; tn < 8; tn++) {
            S[tn][0] *= 0.125f; S[tn][1] *= 0.125f;
            S[tn][2] *= 0.125f; S[tn][3] *= 0.125f;
            mx0 = fmaxf(mx0, fmaxf(S[tn][0], S[tn][1]));
            mx1 = fmaxf(mx1, fmaxf(S[tn][2], S[tn][3]));
        }
        mx0 = fmaxf(mx0, __shfl_xor_sync(0xffffffffu, mx0, 1));
        mx0 = fmaxf(mx0, __shfl_xor_sync(0xffffffffu, mx0, 2));
        mx1 = fmaxf(mx1, __shfl_xor_sync(0xffffffffu, mx1, 1));
        mx1 = fmaxf(mx1, __shfl_xor_sync(0xffffffffu, mx1, 2));
        float mn0 = fmaxf(m0, mx0), mn1 = fmaxf(m1, mx1);
        float cr0 = __expf(m0 - mn0), cr1 = __expf(m1 - mn1);
        float rs0 = 0.f, rs1 = 0.f;
#pragma unroll
        for (int tn = 0; tn < 8; tn++) {
            S[tn][0] = tf32r(__expf(S[tn][0] - mn0));
            S[tn][1] = tf32r(__expf(S[tn][1] - mn0));
            S[tn][2] = tf32r(__expf(S[tn][2] - mn1));
            S[tn][3] = tf32r(__expf(S[tn][3] - mn1));
            rs0 += S[tn][0] + S[tn][1];
            rs1 += S[tn][2] + S[tn][3];
        }
        rs0 += __shfl_xor_sync(0xffffffffu, rs0, 1);
        rs0 += __shfl_xor_sync(0xffffffffu, rs0, 2);
        rs1 += __shfl_xor_sync(0xffffffffu, rs1, 1);
        rs1 += __shfl_xor_sync(0xffffffffu, rs1, 2);
        l0 = l0 * cr0 + rs0;  l1 = l1 * cr1 + rs1;
        m0 = mn0;  m1 = mn1;

#pragma unroll
        for (int tn = 0; tn < 8; tn++) {
            O[tn][0] *= cr0; O[tn][1] *= cr0;
            O[tn][2] *= cr1; O[tn][3] *= cr1;
        }

        // O += P @ V (P a-frags via quad shuffles, V frags via float4)
#pragma unroll
        for (int kp = 0; kp < 4; kp++) {
            int off = (kp >> 1) * 32 + tg * 8 + (kp & 1) * 4;
            float4 vf[8];
#pragma unroll
            for (int tn = 0; tn < 8; tn++)
                vf[tn] = *(const float4*)&Vs[(tn * 8 + g) * 68 + off];
#pragma unroll
            for (int h = 0; h < 2; h++) {
                int ks = kp * 2 + h;
                float e00 = __shfl_sync(0xffffffffu, S[ks][0], srcA);
                float e01 = __shfl_sync(0xffffffffu, S[ks][1], srcA);
                float e10 = __shfl_sync(0xffffffffu, S[ks][2], srcA);
                float e11 = __shfl_sync(0xffffffffu, S[ks][3], srcA);
                float f00 = __shfl_sync(0xffffffffu, S[ks][0], srcB);
                float f01 = __shfl_sync(0xffffffffu, S[ks][1], srcB);
                float f10 = __shfl_sync(0xffffffffu, S[ks][2], srcB);
                float f11 = __shfl_sync(0xffffffffu, S[ks][3], srcB);
                uint32_t a[4];
                a[0] = fau(oddc ? e01 : e00);
                a[1] = fau(oddc ? e11 : e10);
                a[2] = fau(oddc ? f01 : f00);
                a[3] = fau(oddc ? f11 : f10);
#pragma unroll
                for (int tn = 0; tn < 8; tn++) {
                    uint32_t bfr[2];
                    bfr[0] = fau(h ? vf[tn].z : vf[tn].x);
                    bfr[1] = fau(h ? vf[tn].w : vf[tn].y);
                    mma8(O[tn], a, bfr);
                }
            }
        }

        __syncthreads();
        if (kt + 2 < 16)
            attn_load_kv(sbase, b, K, V, kt + 2, tid);
        CP_COMMIT();
    }

    // epilogue -> g_att[n][s][c-perm]
    int n = nh >> 3, head = nh & 7;
    float inv0 = 1.f / l0, inv1 = 1.f / l1;
    int srow0 = q0 + qb + g, srow1 = srow0 + 8;
    float* dst = g_att + (size_t)n * Ss * Cc + head * 64;
#pragma unroll
    for (int tn = 0; tn < 8; tn++) {
        int c = tn * 8 + 2 * tg;
        int cp0 = kperm(c), cp1 = kperm(c + 1);
        dst[(size_t)srow0 * Cc + cp0] = tf32r(O[tn][0] * inv0);
        dst[(size_t)srow0 * Cc + cp1] = tf32r(O[tn][1] * inv0);
        dst[(size_t)srow1 * Cc + cp0] = tf32r(O[tn][2] * inv1);
        dst[(size_t)srow1 * Cc + cp1] = tf32r(O[tn][3] * inv1);
    }
}

// ---------------------------------------------------------------------------
extern "C" void kernel_launch(void* const* d_in, const int* in_sizes, int n_in,
                              void* d_out, int out_size)
{
    const float* x    = (const float*)d_in[0];
    const float* gsc  = (const float*)d_in[1];
    const float* gbi  = (const float*)d_in[2];
    const float* wqkv = (const float*)d_in[3];
    const float* bqkv = (const float*)d_in[4];
    const float* wout = (const float*)d_in[5];
    const float* bout = (const float*)d_in[6];
    float* out = (float*)d_out;

    trans_kernel<<<dim3(D3 / 32, Cc / 32), dim3(32, 8)>>>(wqkv, D3, 0);
    trans_kernel<<<dim3(Cc / 32, Cc / 32), dim3(32, 8)>>>(wout, Cc, 1);

    cudaFuncSetAttribute(gn_kernel, cudaFuncAttributeMaxDynamicSharedMemorySize, 69632);
    gn_kernel<<<Nn * 32, 256, 69632>>>(x, gsc, gbi);

    const int gemm_smem = 27648 * 4;   // 3 stages x 9216 floats
    cudaFuncSetAttribute(gemm_mma, cudaFuncAttributeMaxDynamicSharedMemorySize, gemm_smem);
    gemm_mma<<<dim3(Ss / 128, D3 / 128, Nn), 256, gemm_smem>>>(bqkv, nullptr, nullptr, 0);

    cudaFuncSetAttribute(attn_mma, cudaFuncAttributeMaxDynamicSharedMemorySize, ATT_SMEM);
    attn_mma<<<dim3(Ss / 128, Nn * NHEADS), 256, ATT_SMEM>>>();

    gemm_mma<<<dim3(Ss / 128, Cc / 128, Nn), 256, gemm_smem>>>(bout, x, out, 1);
}